// round 15
// baseline (speedup 1.0000x reference)
#include <cuda_runtime.h>
#include <cuda_fp16.h>

#define NN 50000
#define NE 600000
#define DD 128
#define SCAN_B 1024
#define SCAN_G ((NN + SCAN_B - 1) / SCAN_B)   // 49
#define LDA 132                                // padded halves/row in smem (bank spread)
#define GEMM_SMEM (2 * 128 * LDA * 2)          // A tile + Wt tile, 67584 B

// ---------------- scratch (static device globals; no allocation) ----------------
__device__ __half g_xwh[NN * DD];               // fp16(x @ W), 12.8 MB (L2-resident)
__device__ int    g_degi[NN];                   // zero at load; fill re-zeroes
__device__ int    g_start[NN];
__device__ int    g_cur[NN];
__device__ unsigned int g_adj[NE];              // src per edge (CSR by dst)
__device__ float  g_dinv[NN];
__device__ int    g_bsum[SCAN_G];
__device__ unsigned int g_ready;                // scanf sync; fill resets to 0
__device__ float  g_sum[DD];                    // zeroed in scanf each run
__device__ float  g_sumsq[DD];

// ---- local int64/int32 detection: values < 50000 => int64 odd words all zero ----
__device__ __forceinline__ int detect_is64(const unsigned int* __restrict__ e) {
    int is64 = 1;
    #pragma unroll
    for (int i = 0; i < 16; i++)
        if (e[2 * i + 1] != 0u) { is64 = 0; break; }
    return is64;
}

// ---------------- degree over dst ----------------
__global__ void deg_kernel(const unsigned int* __restrict__ e) {
    __shared__ int s64;
    if (threadIdx.x == 0) s64 = detect_is64(e);
    __syncthreads();
    int t = blockIdx.x * blockDim.x + threadIdx.x;
    if (t >= NE) return;
    int d;
    if (s64) d = (int)((const long long*)e)[NE + t];
    else     d = ((const int*)e)[NE + t];
    atomicAdd(&g_degi[d], 1);
}

// ------- fused scan: dinv + block scan + cross-block sync + start/cur ------------
__global__ void __launch_bounds__(SCAN_B) scanf_kernel() {
    __shared__ int wsums[32];
    __shared__ int bpart[2];
    const int tid = threadIdx.x, lane = tid & 31, wid = tid >> 5;
    const int bid = blockIdx.x;

    if (bid == 0 && tid < DD) { g_sum[tid] = 0.0f; g_sumsq[tid] = 0.0f; }

    const int i = bid * SCAN_B + tid;
    int d = (i < NN) ? g_degi[i] : 0;
    if (i < NN) g_dinv[i] = rsqrtf((float)d + 1.0f);   // +1 = self loop

    int v = d;
    #pragma unroll
    for (int o = 1; o < 32; o <<= 1) {
        int t = __shfl_up_sync(0xffffffffu, v, o);
        if (lane >= o) v += t;
    }
    if (lane == 31) wsums[wid] = v;
    __syncthreads();
    if (wid == 0) {
        int wv = wsums[lane];
        #pragma unroll
        for (int o = 1; o < 32; o <<= 1) {
            int t = __shfl_up_sync(0xffffffffu, wv, o);
            if (lane >= o) wv += t;
        }
        wsums[lane] = wv;
    }
    __syncthreads();

    if (tid == 0) {
        g_bsum[bid] = wsums[31];
        __threadfence();
        atomicAdd(&g_ready, 1u);
        volatile unsigned int* r = &g_ready;
        while (*r < (unsigned)SCAN_G) __nanosleep(32);
        __threadfence();
    }
    __syncthreads();

    if (tid < 64) {
        int t = (tid < bid) ? g_bsum[tid] : 0;
        #pragma unroll
        for (int o = 16; o > 0; o >>= 1) t += __shfl_down_sync(0xffffffffu, t, o);
        if ((tid & 31) == 0) bpart[tid >> 5] = t;
    }
    __syncthreads();

    if (i < NN) {
        int excl = bpart[0] + bpart[1] + (wid > 0 ? wsums[wid - 1] : 0) + (v - d);
        g_start[i] = excl;
        g_cur[i]   = excl;
    }
}

// -------- adjacency fill; re-zero degi + reset scan sync for next replay ---------
__global__ void fill_kernel(const unsigned int* __restrict__ e) {
    __shared__ int s64;
    if (threadIdx.x == 0) s64 = detect_is64(e);
    __syncthreads();
    int t = blockIdx.x * blockDim.x + threadIdx.x;
    if (t >= NE) return;
    if (t < NN) g_degi[t] = 0;
    if (t == 0) g_ready = 0u;
    int s, d;
    if (s64) {
        s = (int)((const long long*)e)[t];
        d = (int)((const long long*)e)[NE + t];
    } else {
        s = ((const int*)e)[t];
        d = ((const int*)e)[NE + t];
    }
    int p = atomicAdd(&g_cur[d], 1);
    g_adj[p] = (unsigned int)s;
}

// ---- GEMM via tensor cores: g_xwh = fp16(x @ W), mma.sync m16n8k16 f16/f32 ------
__global__ void __launch_bounds__(256) gemm_tc_kernel(const float* __restrict__ x,
                                                      const float* __restrict__ W) {
    extern __shared__ __half smem[];
    __half* As = smem;                  // [128][LDA] x tile (row-major, fp16)
    __half* Bs = smem + 128 * LDA;      // [128][LDA] Wt: Bs[n][k] = W[k][n] (fp16)

    const int tid = threadIdx.x;
    const int r0  = blockIdx.x * 128;

    for (int i = tid; i < 128 * 32; i += 256) {
        int row = i >> 5, c4 = i & 31;
        float4 v = make_float4(0.f, 0.f, 0.f, 0.f);
        if (r0 + row < NN) v = ((const float4*)x)[(size_t)(r0 + row) * 32 + c4];
        __half2 h01 = __floats2half2_rn(v.x, v.y);
        __half2 h23 = __floats2half2_rn(v.z, v.w);
        *(uint2*)(As + row * LDA + c4 * 4) =
            make_uint2(*(unsigned*)&h01, *(unsigned*)&h23);
    }
    for (int i = tid; i < 128 * 128; i += 256) {
        int k = i >> 7, n = i & 127;
        Bs[n * LDA + k] = __float2half_rn(W[i]);
    }
    __syncthreads();

    const int warp = tid >> 5, lane = tid & 31;
    const int gid = lane >> 2, tig = lane & 3;
    const int wr = warp * 16;

    float c[16][4];
    #pragma unroll
    for (int t = 0; t < 16; t++) { c[t][0] = c[t][1] = c[t][2] = c[t][3] = 0.f; }

    #pragma unroll
    for (int ks = 0; ks < 8; ks++) {
        const int k0 = ks * 16;
        unsigned a0 = *(unsigned*)(As + (wr + gid)     * LDA + k0 + 2 * tig);
        unsigned a1 = *(unsigned*)(As + (wr + gid + 8) * LDA + k0 + 2 * tig);
        unsigned a2 = *(unsigned*)(As + (wr + gid)     * LDA + k0 + 2 * tig + 8);
        unsigned a3 = *(unsigned*)(As + (wr + gid + 8) * LDA + k0 + 2 * tig + 8);
        #pragma unroll
        for (int t = 0; t < 16; t++) {
            unsigned b0 = *(unsigned*)(Bs + (t * 8 + gid) * LDA + k0 + 2 * tig);
            unsigned b1 = *(unsigned*)(Bs + (t * 8 + gid) * LDA + k0 + 2 * tig + 8);
            asm volatile(
                "mma.sync.aligned.m16n8k16.row.col.f32.f16.f16.f32 "
                "{%0,%1,%2,%3}, {%4,%5,%6,%7}, {%8,%9}, {%0,%1,%2,%3};"
                : "+f"(c[t][0]), "+f"(c[t][1]), "+f"(c[t][2]), "+f"(c[t][3])
                : "r"(a0), "r"(a1), "r"(a2), "r"(a3), "r"(b0), "r"(b1));
        }
    }

    const int row0 = r0 + wr + gid;
    const int row1 = row0 + 8;
    #pragma unroll
    for (int t = 0; t < 16; t++) {
        const int col = t * 8 + 2 * tig;
        if (row0 < NN) {
            __half2 h = __floats2half2_rn(c[t][0], c[t][1]);
            *(unsigned*)(g_xwh + (size_t)row0 * DD + col) = *(unsigned*)&h;
        }
        if (row1 < NN) {
            __half2 h = __floats2half2_rn(c[t][2], c[t][3]);
            *(unsigned*)(g_xwh + (size_t)row1 * DD + col) = *(unsigned*)&h;
        }
    }
}

// ---- gather: warp/node, 2 edges in flight; BN stats in smem; 5 blocks/SM --------
__device__ __forceinline__ float2 h2f(unsigned int h) {
    __half2 hh = *(__half2*)&h;
    return __half22float2(hh);
}

__global__ void __launch_bounds__(256, 5) gather_kernel(const float* __restrict__ bias,
                                                        float* __restrict__ z) {
    __shared__ float rs[8][DD];    // per-warp BN sum partials
    __shared__ float rq[8][DD];    // per-warp BN sumsq partials

    const int tid   = threadIdx.x;
    const int lane  = tid & 31;
    const int wid   = tid >> 5;
    const int g     = lane >> 4;   // half-warp id (0/1): edge parity
    const int hl    = lane & 15;   // lane in half-warp -> cols 8*hl..8*hl+7
    const int warpg = (blockIdx.x * 256 + tid) >> 5;
    const int nwarp = gridDim.x * 8;

    // zero smem stat accumulators: 2048 floats / 256 threads
    #pragma unroll
    for (int k = 0; k < 4; k++) {
        ((float*)rs)[tid + k * 256] = 0.f;
        ((float*)rq)[tid + k * 256] = 0.f;
    }
    __syncthreads();

    const uint4*  __restrict__ xws   = (const uint4*)g_xwh;   // row = 16 uint4
    const float4* __restrict__ bias4 = (const float4*)bias;
    float4*       __restrict__ z4    = (float4*)z;

    const float4 b0 = bias4[2 * hl];
    const float4 b1 = bias4[2 * hl + 1];

    for (int node = warpg; node < NN; node += nwarp) {
        const int beg = g_start[node];
        const int end = g_cur[node];
        const float di = g_dinv[node];

        float a[8];
        #pragma unroll
        for (int k = 0; k < 8; k++) a[k] = 0.f;

        // self loop: xwh[node]*di here; outer *di below makes it di^2 (half-warp 0)
        if (g == 0) {
            uint4 r = __ldcg(&xws[(size_t)node * 16 + hl]);
            float2 p0 = h2f(r.x), p1 = h2f(r.y), p2 = h2f(r.z), p3 = h2f(r.w);
            a[0] = p0.x * di; a[1] = p0.y * di; a[2] = p1.x * di; a[3] = p1.y * di;
            a[4] = p2.x * di; a[5] = p2.y * di; a[6] = p3.x * di; a[7] = p3.y * di;
        }

        for (int base = beg; base < end; base += 32) {
            const int cnt = min(32, end - base);
            unsigned int sv = (lane < cnt) ? g_adj[base + lane] : 0u;  // coalesced
            float dv = __ldg(&g_dinv[sv]);                              // L1-hot table
            #pragma unroll 4
            for (int j = 0; j < cnt; j += 2) {
                int ei = j + g;
                unsigned int sj = __shfl_sync(0xffffffffu, sv, ei & 31);
                float        nj = __shfl_sync(0xffffffffu, dv, ei & 31);
                if (ei < cnt) {
                    uint4 r = __ldcg(&xws[(size_t)sj * 16 + hl]);
                    float2 p0 = h2f(r.x), p1 = h2f(r.y), p2 = h2f(r.z), p3 = h2f(r.w);
                    a[0] += p0.x * nj; a[1] += p0.y * nj;
                    a[2] += p1.x * nj; a[3] += p1.y * nj;
                    a[4] += p2.x * nj; a[5] += p2.y * nj;
                    a[6] += p3.x * nj; a[7] += p3.y * nj;
                }
            }
        }

        // combine the two half-warps
        #pragma unroll
        for (int k = 0; k < 8; k++) a[k] += __shfl_xor_sync(0xffffffffu, a[k], 16);

        if (g == 0) {
            const int c0 = hl * 8;
            float4 v0, v1;
            v0.x = fmaxf(a[0] * di + b0.x, 0.0f);
            v0.y = fmaxf(a[1] * di + b0.y, 0.0f);
            v0.z = fmaxf(a[2] * di + b0.z, 0.0f);
            v0.w = fmaxf(a[3] * di + b0.w, 0.0f);
            v1.x = fmaxf(a[4] * di + b1.x, 0.0f);
            v1.y = fmaxf(a[5] * di + b1.y, 0.0f);
            v1.z = fmaxf(a[6] * di + b1.z, 0.0f);
            v1.w = fmaxf(a[7] * di + b1.w, 0.0f);
            z4[(size_t)node * 32 + 2 * hl]     = v0;
            z4[(size_t)node * 32 + 2 * hl + 1] = v1;
            // BN partials into smem (each lane owns its 8 columns of rs[wid])
            rs[wid][c0 + 0] += v0.x; rq[wid][c0 + 0] += v0.x * v0.x;
            rs[wid][c0 + 1] += v0.y; rq[wid][c0 + 1] += v0.y * v0.y;
            rs[wid][c0 + 2] += v0.z; rq[wid][c0 + 2] += v0.z * v0.z;
            rs[wid][c0 + 3] += v0.w; rq[wid][c0 + 3] += v0.w * v0.w;
            rs[wid][c0 + 4] += v1.x; rq[wid][c0 + 4] += v1.x * v1.x;
            rs[wid][c0 + 5] += v1.y; rq[wid][c0 + 5] += v1.y * v1.y;
            rs[wid][c0 + 6] += v1.z; rq[wid][c0 + 6] += v1.z * v1.z;
            rs[wid][c0 + 7] += v1.w; rq[wid][c0 + 7] += v1.w * v1.w;
        }
    }

    __syncthreads();
    if (tid < DD) {
        float s = 0.f, q = 0.f;
        #pragma unroll
        for (int w = 0; w < 8; w++) { s += rs[w][tid]; q += rq[w][tid]; }
        atomicAdd(&g_sum[tid], s);
        atomicAdd(&g_sumsq[tid], q);
    }
}

// --------- fused BN params + normalize + dropout ---------------------------------
__global__ void __launch_bounds__(256) final_kernel(const float* __restrict__ gamma,
                                                    const float* __restrict__ beta,
                                                    const float* __restrict__ u,
                                                    float* __restrict__ z) {
    __shared__ float sc[DD], sh[DD];
    const int tid = threadIdx.x;
    if (tid < DD) {
        float mean = g_sum[tid] * (1.0f / NN);
        float var  = g_sumsq[tid] * (1.0f / NN) - mean * mean;
        float s    = gamma[tid] * rsqrtf(var + 1e-5f);
        sc[tid] = s;
        sh[tid] = beta[tid] - mean * s;
    }
    __syncthreads();

    int gid = blockIdx.x * blockDim.x + tid;
    if (gid >= NN * 32) return;
    int j4 = (gid & 31) * 4;

    float4 v  = ((const float4*)z)[gid];
    float4 uu = ((const float4*)u)[gid];
    const float inv_keep = 1.0f / 0.9f;

    float4 r;
    r.x = (uu.x > 0.1f) ? (v.x * sc[j4 + 0] + sh[j4 + 0]) * inv_keep : 0.0f;
    r.y = (uu.y > 0.1f) ? (v.y * sc[j4 + 1] + sh[j4 + 1]) * inv_keep : 0.0f;
    r.z = (uu.z > 0.1f) ? (v.z * sc[j4 + 2] + sh[j4 + 2]) * inv_keep : 0.0f;
    r.w = (uu.w > 0.1f) ? (v.w * sc[j4 + 3] + sh[j4 + 3]) * inv_keep : 0.0f;
    ((float4*)z)[gid] = r;
}

// --------- launch: gemm_tc (s2) ∥ deg -> scanf -> fill; join; gather; final ------
extern "C" void kernel_launch(void* const* d_in, const int* in_sizes, int n_in,
                              void* d_out, int out_size) {
    const float* x      = (const float*)d_in[0];
    const float* weight = (const float*)d_in[1];
    const float* bias   = (const float*)d_in[2];
    const float* gamma  = (const float*)d_in[3];
    const float* beta   = (const float*)d_in[4];
    const float* drop_u = (const float*)d_in[5];
    const unsigned int* eidx = (const unsigned int*)d_in[6];

    float* z = (float*)d_out;

    static cudaStream_t s2 = nullptr;
    static cudaEvent_t evf = nullptr, evj = nullptr;
    if (s2 == nullptr) {
        cudaStreamCreateWithFlags(&s2, cudaStreamNonBlocking);
        cudaEventCreateWithFlags(&evf, cudaEventDisableTiming);
        cudaEventCreateWithFlags(&evj, cudaEventDisableTiming);
        cudaFuncSetAttribute(gemm_tc_kernel,
                             cudaFuncAttributeMaxDynamicSharedMemorySize, GEMM_SMEM);
    }

    // fork: tensor-core GEMM depends only on inputs; hidden under the preproc chain
    cudaEventRecord(evf, 0);
    cudaStreamWaitEvent(s2, evf, 0);
    gemm_tc_kernel<<<(NN + 127) / 128, 256, GEMM_SMEM, s2>>>(x, weight);
    cudaEventRecord(evj, s2);

    // main chain: edge preprocessing
    deg_kernel<<<(NE + 255) / 256, 256>>>(eidx);
    scanf_kernel<<<SCAN_G, SCAN_B>>>();
    fill_kernel<<<(NE + 255) / 256, 256>>>(eidx);

    // join: gather needs CSR + fp16 rows
    cudaStreamWaitEvent(0, evj, 0);
    gather_kernel<<<740, 256>>>(bias, z);

    // epilogue
    final_kernel<<<(NN * 32 + 255) / 256, 256>>>(gamma, beta, drop_u, z);
}